// round 8
// baseline (speedup 1.0000x reference)
#include <cuda_runtime.h>
#include <cstdint>

// ---------------------------------------------------------------------------
// SCAConv decomposition (same math as R2-R6):
// out[b,o,l] = bias[o] + sum_i xu*kernel[o,i] + sum_i xu*b2[(l&31)*144+i]
//            + sum_j H[o*128+(l>>5), j] * G[b,l,j]
// G[b,l,j] = sum_i xu[b,i,l] * W2[((l&31)*144+i)*32 + j]
//
// R7: thread tile widened to 8 batches x 8 cols (halves x-LDS per FMA);
// 512 threads kept by splitting the i-range (c<8 / c>=8, disjoint W2 rows,
// no stream duplication); FMA2-ized H*G epilogue.
// ---------------------------------------------------------------------------

#define XS_OFF   0
#define XS_RSTR  35
#define XS_SIZE  (48*XS_RSTR*8)        // 13440 floats, batch innermost
#define HS_OFF   (XS_OFF + XS_SIZE)
#define HS_SIZE  (32*32)
#define BIAS_OFF (HS_OFF + HS_SIZE)
#define BIAS_SIZE 32
#define CS_OFF   (BIAS_OFF + BIAS_SIZE)
#define CS_LSTR  68                    // per-lm: 32 G + 32 conv + 1 t + 3 pad
#define CS_BSTR  (32*CS_LSTR)
#define CS_HALF  (8*CS_BSTR)           // one i-half partial block (17408)
#define CS_SIZE  (2*CS_HALF)
#define SMEM_FLOATS (CS_OFF + CS_SIZE) // 49312 floats = 197.2 KB

__device__ float g_kT[144*32];         // kernel transposed: kT[i][o]

__global__ void prep_kernel(const float* __restrict__ kern) {
    int idx = blockIdx.x * 256 + threadIdx.x;
    if (idx < 4608) {
        int i = idx >> 5, o = idx & 31;
        g_kT[idx] = kern[o*144 + i];
    }
}

typedef unsigned long long ull;

#define PACK2(d, s)      asm("mov.b64 %0, {%1, %1};" : "=l"(d) : "f"(s))
#define PACKAB(d, a, b)  asm("mov.b64 %0, {%1, %2};" : "=l"(d) : "f"(a), "f"(b))
#define UNPACK2(lo, hi, v) asm("mov.b64 {%0, %1}, %2;" : "=f"(lo), "=f"(hi) : "l"(v))
#define FMA2(acc, a, b)  asm("fma.rn.f32x2 %0, %1, %2, %0;" : "+l"(acc) : "l"(a), "l"(b))

__global__ __launch_bounds__(512, 1)
void sca_kernel(const float* __restrict__ x, const float* __restrict__ bias,
                const float* __restrict__ cpar,
                const float* __restrict__ W1, const float* __restrict__ b1,
                const float* __restrict__ W2, const float* __restrict__ b2,
                float* __restrict__ out)
{
    extern __shared__ float sm[];
    float* xs = sm + XS_OFF;
    float* Hs = sm + HS_OFF;
    float* bs = sm + BIAS_OFF;
    float* Cs = sm + CS_OFF;

    const int tid = threadIdx.x;
    const int lh  = blockIdx.x;
    const int R   = lh >> 1;
    const int C0  = (lh & 1) * 32;

    // ---------- setup: x patch, batch-innermost ----------
    for (int idx = tid; idx < 8*16*3*34; idx += 512) {
        int cc = idx % 34;
        int t2 = idx / 34;
        int kr = t2 % 3;  t2 /= 3;
        int c  = t2 % 16;
        int b  = t2 / 16;
        int r   = R - 1 + kr;
        int col = C0 - 1 + cc;
        float v = 0.f;
        if (r >= 0 && r < 64 && col >= 0 && col < 64)
            v = x[((b*16 + c)*64 + r)*64 + col];
        xs[((c*3 + kr)*XS_RSTR + cc)*8 + b] = v;
    }

    // ---------- H rows: H[o*128+lh][j] ----------
    {
        int o  = tid >> 4;
        int jh = tid & 15;
        int p  = o*128 + lh;
        float inp[12];
        inp[0] = (float)(p >> 6) * (1.f/64.f);
        inp[1] = 1.f - inp[0];
        inp[2] = (float)(p & 63) * (1.f/64.f);
        inp[3] = 1.f - inp[2];
        #pragma unroll
        for (int k = 0; k < 8; k++) inp[4+k] = cpar[k];
        #pragma unroll
        for (int jj = 0; jj < 2; jj++) {
            int j = jh*2 + jj;
            float s = b1[j];
            #pragma unroll
            for (int k = 0; k < 12; k++) s += W1[j*12 + k] * inp[k];
            Hs[o*32 + j] = fmaxf(s, 0.f);
        }
    }
    if (tid < 32) bs[tid] = bias[tid];
    __syncthreads();

    // ---------- main loop: 8 batches x 8 cols, i-range split in halves ----------
    // tid = half*256 + part*128 + lm*4 + cq
    //   half: c in [half*8, half*8+8)
    //   part 0: G cols j = cq*8..+7 (W2, L2-hot) ; part 1: conv cols (g_kT)
    {
        const int half = tid >> 8;
        const int rest = tid & 255;
        const int part = rest >> 7;
        const int lm   = (rest >> 2) & 31;
        const int cq   = rest & 3;

        const float* wp = part ? (g_kT + cq*8) : (W2 + lm*4608 + cq*8);
        const float* xp = xs + lm*8;

        ull acc[8][4];   // [col n][batch pair bp]
        #pragma unroll
        for (int n = 0; n < 8; n++)
            #pragma unroll
            for (int bp = 0; bp < 4; bp++) acc[n][bp] = 0ull;

        const int c0 = half*8;
        #pragma unroll 2
        for (int c = c0; c < c0 + 8; ++c) {
            const float* xc = xp + c*(3*XS_RSTR*8);
            const float* wc = wp + c*(9*32);
            #pragma unroll
            for (int kr = 0; kr < 3; ++kr) {
                #pragma unroll
                for (int kc = 0; kc < 3; ++kc) {
                    const float* xr = xc + (kr*XS_RSTR + kc)*8;
                    ulonglong2 xa = *(const ulonglong2*)(xr);      // b0..b3
                    ulonglong2 xb = *(const ulonglong2*)(xr + 4);  // b4..b7
                    const float* w = wc + (kr*3 + kc)*32;
                    float4 w0 = *(const float4*)(w);
                    float4 w1 = *(const float4*)(w + 4);
                    ull wpk[8];
                    PACK2(wpk[0], w0.x); PACK2(wpk[1], w0.y);
                    PACK2(wpk[2], w0.z); PACK2(wpk[3], w0.w);
                    PACK2(wpk[4], w1.x); PACK2(wpk[5], w1.y);
                    PACK2(wpk[6], w1.z); PACK2(wpk[7], w1.w);
                    #pragma unroll
                    for (int n = 0; n < 8; n++) {
                        FMA2(acc[n][0], xa.x, wpk[n]);
                        FMA2(acc[n][1], xa.y, wpk[n]);
                        FMA2(acc[n][2], xb.x, wpk[n]);
                        FMA2(acc[n][3], xb.y, wpk[n]);
                    }
                }
            }
        }

        // unpack -> per-batch stores into this half's partial block
        float* cb = Cs + half*CS_HALF + lm*CS_LSTR + part*32 + cq*8;
        #pragma unroll
        for (int bp = 0; bp < 4; bp++) {
            float f0[8], f1[8];
            #pragma unroll
            for (int n = 0; n < 8; n++) UNPACK2(f0[n], f1[n], acc[n][bp]);
            *(float4*)(cb + (2*bp)*CS_BSTR)       = make_float4(f0[0], f0[1], f0[2], f0[3]);
            *(float4*)(cb + (2*bp)*CS_BSTR + 4)   = make_float4(f0[4], f0[5], f0[6], f0[7]);
            *(float4*)(cb + (2*bp+1)*CS_BSTR)     = make_float4(f1[0], f1[1], f1[2], f1[3]);
            *(float4*)(cb + (2*bp+1)*CS_BSTR + 4) = make_float4(f1[4], f1[5], f1[6], f1[7]);
        }
    }

    // ---------- t-term, distributed: 256 (b,lm) outputs x 2 i-halves ----------
    {
        const int half = tid >> 8;
        const int idx  = tid & 255;
        const int b    = idx & 7;
        const int lm2  = idx >> 3;
        const float* bp2 = b2 + lm2*144;
        float tacc = 0.f;
        #pragma unroll 2
        for (int c = half*8; c < half*8 + 8; ++c) {
            #pragma unroll
            for (int kr = 0; kr < 3; ++kr) {
                #pragma unroll
                for (int kc = 0; kc < 3; ++kc) {
                    float xv = xs[((c*3 + kr)*XS_RSTR + lm2 + kc)*8 + b];
                    tacc += xv * bp2[c*9 + kr*3 + kc];
                }
            }
        }
        Cs[half*CS_HALF + b*CS_BSTR + lm2*CS_LSTR + 64] = tacc;
    }
    __syncthreads();

    // ---------- epilogue: out = bias + t + conv + H·G (FMA2 over j-pairs) ----------
    {
        int b   = tid >> 6;
        int oh  = (tid >> 5) & 1;
        int lm3 = tid & 31;
        const float* cb0 = Cs + b*CS_BSTR + lm3*CS_LSTR;
        const float* cb1 = cb0 + CS_HALF;

        ull gp[16];                    // g as 16 packed j-pairs
        #pragma unroll
        for (int q = 0; q < 8; q++) {
            float4 v0 = *(const float4*)(cb0 + q*4);
            float4 v1 = *(const float4*)(cb1 + q*4);
            PACKAB(gp[2*q],   v0.x + v1.x, v0.y + v1.y);
            PACKAB(gp[2*q+1], v0.z + v1.z, v0.w + v1.w);
        }
        float cw[16];
        #pragma unroll
        for (int q = 0; q < 4; q++) {
            float4 v0 = *(const float4*)(cb0 + 32 + oh*16 + q*4);
            float4 v1 = *(const float4*)(cb1 + 32 + oh*16 + q*4);
            cw[q*4+0] = v0.x + v1.x; cw[q*4+1] = v0.y + v1.y;
            cw[q*4+2] = v0.z + v1.z; cw[q*4+3] = v0.w + v1.w;
        }
        float tv = cb0[64] + cb1[64];

        float* ob = out + b*(32*4096) + (oh*16)*4096 + lh*32 + lm3;
        #pragma unroll
        for (int oo = 0; oo < 16; oo++) {
            int o = oh*16 + oo;
            const ulonglong2* h2 = (const ulonglong2*)(Hs + o*32);
            ull a2 = 0ull;
            #pragma unroll
            for (int q = 0; q < 8; q++) {
                ulonglong2 hv = h2[q];
                FMA2(a2, hv.x, gp[2*q]);
                FMA2(a2, hv.y, gp[2*q+1]);
            }
            float lo, hi; UNPACK2(lo, hi, a2);
            ob[oo*4096] = bs[o] + tv + cw[oo] + lo + hi;
        }
    }
}

extern "C" void kernel_launch(void* const* d_in, const int* in_sizes, int n_in,
                              void* d_out, int out_size)
{
    const float* x    = (const float*)d_in[0];   // (8,16,64,64)
    const float* kern = (const float*)d_in[1];   // (32,144)
    const float* bias = (const float*)d_in[2];   // (32,)
    const float* cpar = (const float*)d_in[3];   // (1,8)
    const float* W1   = (const float*)d_in[4];   // (32,12)
    const float* b1   = (const float*)d_in[5];   // (32,)
    const float* W2   = (const float*)d_in[6];   // (4608,32)
    const float* b2   = (const float*)d_in[7];   // (4608,)
    float* out = (float*)d_out;                  // (8,32,64,64)

    prep_kernel<<<18, 256>>>(kern);
    cudaFuncSetAttribute(sca_kernel, cudaFuncAttributeMaxDynamicSharedMemorySize,
                         SMEM_FLOATS * 4);
    sca_kernel<<<128, 512, SMEM_FLOATS * 4>>>(x, bias, cpar, W1, b1, W2, b2, out);
}